// round 13
// baseline (speedup 1.0000x reference)
#include <cuda_runtime.h>
#include <math.h>
#include <stdint.h>

#define BB    256
#define TT    1000
#define NIN   128
#define UNITS 512

#define CACHE_ROWS   96                      // words 0..2 cached in smem
#define CACHE_BYTES  (CACHE_ROWS * UNITS * 4)        // 196608
#define OFF_MASK     CACHE_BYTES                     // u32 [2][2][16]
#define OFF_CNT      (OFF_MASK + 256)                // int [4][2]
#define OFF_ENT      (OFF_CNT + 32)                  // uint4 [4][128]
#define SMEM_TOTAL   (OFF_ENT + 4 * 128 * 16)        // 205088 B

// scratch
__device__ float g_iin[(size_t)BB * TT * UNITS];
__device__ float g_wrec[(size_t)UNITS * UNITS];

// ---------------------------------------------------------------------------
// Prep: diag-zeroed W_rec copy (reference zeroes diag before matmul).
// ---------------------------------------------------------------------------
__global__ void prep_wrec_kernel(const float* __restrict__ W_rec) {
    int idx = blockIdx.x * blockDim.x + threadIdx.x;
    int row = idx >> 9, col = idx & 511;
    g_wrec[idx] = (row == col) ? 0.0f : W_rec[idx];
}

// ---------------------------------------------------------------------------
// Phase 1: i_in = X @ W_in — R9 GEMM verbatim (bit-frozen serial ascending-k
// FMA chain; ~0.75 ms).
// ---------------------------------------------------------------------------
#define GTM 128
#define GTN 128
#define GTK 32

__global__ __launch_bounds__(256) void gemm_kernel(const float* __restrict__ X,
                                                   const float* __restrict__ Wm) {
    __shared__ float As[GTK][GTM + 4];
    __shared__ float Bs[GTK][GTN];
    const int bm = blockIdx.y * GTM;
    const int bn = blockIdx.x * GTN;
    const int tid = threadIdx.x;
    const int tx = tid & 15, ty = tid >> 4;

    float acc[8][8] = {};

    for (int kc = 0; kc < NIN; kc += GTK) {
        #pragma unroll
        for (int i = 0; i < 4; i++) {
            int idx = tid + i * 256;
            int m  = idx >> 3;
            int k4 = idx & 7;
            float4 vv = *(const float4*)(X + (size_t)(bm + m) * NIN + kc + k4 * 4);
            As[k4 * 4 + 0][m] = vv.x;
            As[k4 * 4 + 1][m] = vv.y;
            As[k4 * 4 + 2][m] = vv.z;
            As[k4 * 4 + 3][m] = vv.w;
        }
        #pragma unroll
        for (int i = 0; i < 4; i++) {
            int idx = tid + i * 256;
            int k  = idx >> 5;
            int n4 = idx & 31;
            *(float4*)(&Bs[k][n4 * 4]) =
                *(const float4*)(Wm + (size_t)(kc + k) * UNITS + bn + n4 * 4);
        }
        __syncthreads();

        #pragma unroll
        for (int k = 0; k < GTK; k++) {
            float a[8], b[8];
            *(float4*)(a)     = *(const float4*)(&As[k][ty * 8]);
            *(float4*)(a + 4) = *(const float4*)(&As[k][ty * 8 + 4]);
            *(float4*)(b)     = *(const float4*)(&Bs[k][tx * 8]);
            *(float4*)(b + 4) = *(const float4*)(&Bs[k][tx * 8 + 4]);
            #pragma unroll
            for (int i = 0; i < 8; i++)
                #pragma unroll
                for (int j = 0; j < 8; j++)
                    acc[i][j] = fmaf(a[i], b[j], acc[i][j]);
        }
        __syncthreads();
    }

    #pragma unroll
    for (int i = 0; i < 8; i++) {
        float* crow = g_iin + (size_t)(bm + ty * 8 + i) * UNITS + bn + tx * 8;
        __stcs((float4*)(crow),     *(float4*)(&acc[i][0]));
        __stcs((float4*)(crow + 4), *(float4*)(&acc[i][4]));
    }
}

// ---------------------------------------------------------------------------
// Phase 2: ALIF scan, batch-PAIR per CTA (128 CTAs x 512 threads, thread=unit)
// + 96-row smem-resident W_rec prefix.
// Bit-frozen arithmetic: per batch, per slice s (byte s of each mask word),
// ascending (word, bit) chain; union-row iteration with fmaf(zbit,w,acc)
// preserves it exactly (fmaf(1,w,a)=fadd_rn, fmaf(0,w,a)=a). Cached sublist
// (words 0..2) precedes gmem sublist (words 3..15) = frozen ascending order.
// ---------------------------------------------------------------------------
extern __shared__ char s_dyn[];

__global__ __launch_bounds__(512) void scan_kernel(float* __restrict__ out,
                                                   float decay, float omd,
                                                   float decay_b, float omdb) {
    float*    s_cache = (float*)s_dyn;                       // [96][512]
    unsigned* s_mask  = (unsigned*)(s_dyn + OFF_MASK);       // [buf][batch][16]
    int*      s_cnt   = (int*)(s_dyn + OFF_CNT);             // [slice][2]
    uint4*    s_ent   = (uint4*)(s_dyn + OFF_ENT);           // [slice][128]

    const int tid  = threadIdx.x;
    const int g    = blockIdx.x;          // pair id: batches 2g, 2g+1
    const int warp = tid >> 5;
    const int lane = tid & 31;

    // load W_rec rows 0..95 into smem (float4)
    {
        const float4* src = (const float4*)g_wrec;
        float4* dst = (float4*)s_cache;
        for (int i = tid; i < CACHE_ROWS * UNITS / 4; i += 512)
            dst[i] = src[i];
    }
    if (tid < 32) { s_mask[tid] = 0u; s_mask[32 + tid] = 0u; }
    __syncthreads();

    float vA = 0.f, bA = 0.f, zA = 0.f;
    float vB = 0.f, bB = 0.f, zB = 0.f;

    const char* colg = (const char*)g_wrec + ((size_t)tid << 2);
    const char* colc = (const char*)s_cache + ((size_t)tid << 2);
    const float* iptrA = g_iin + (size_t)(2 * g)     * TT * UNITS + tid;
    const float* iptrB = g_iin + (size_t)(2 * g + 1) * TT * UNITS + tid;
    float* optrA = out + (size_t)(2 * g)     * TT * UNITS + tid;
    float* optrB = out + (size_t)(2 * g + 1) * TT * UNITS + tid;

    for (int t = 0; t < TT; t++) {
        const int buf = t & 1;
        float inpA = __ldcs(iptrA + (size_t)t * UNITS);
        float inpB = __ldcs(iptrB + (size_t)t * UNITS);

        // ---- compaction: warp s (<4) builds slice-s union list, split into
        //      cached (words 0..2) and gmem (words 3..15) sublists, each in
        //      frozen ascending (word, bit-in-byte) order ----
        if (warp < 4) {
            const unsigned* mAw = &s_mask[buf * 32];
            const unsigned* mBw = &s_mask[buf * 32 + 16];
            unsigned byteA = 0, byteB = 0;
            if (lane < 16) {
                byteA = (mAw[lane] >> (warp * 8)) & 0xFFu;
                byteB = (mBw[lane] >> (warp * 8)) & 0xFFu;
            }
            unsigned un = byteA | byteB;
            int c  = __popc(un);
            int cc = (lane < 3) ? c : 0;     // cached words
            int cg = (lane >= 3) ? c : 0;    // gmem words
            int sc = cc, sg = cg;
            #pragma unroll
            for (int off = 1; off < 32; off <<= 1) {
                int n1 = __shfl_up_sync(0xffffffffu, sc, off);
                int n2 = __shfl_up_sync(0xffffffffu, sg, off);
                if (lane >= off) { sc += n1; sg += n2; }
            }
            uint4* ent = &s_ent[warp * 128];
            int pos = (lane < 3) ? (sc - cc) : (24 + sg - cg);
            unsigned mm = un;
            while (mm) {
                int j = __ffs(mm) - 1; mm &= mm - 1;
                int row = lane * 32 + warp * 8 + j;
                float f1 = ((byteA >> j) & 1u) ? 1.0f : 0.0f;
                float f2 = ((byteB >> j) & 1u) ? 1.0f : 0.0f;
                ent[pos++] = make_uint4((unsigned)(row << 11),
                                        __float_as_uint(f1),
                                        __float_as_uint(f2), 0u);
            }
            if (lane == 15) { s_cnt[warp * 2] = sc; s_cnt[warp * 2 + 1] = sg; }
        }
        __syncthreads();

        // ---- per-slice sums: cached sublist then gmem sublist ----
        float pA[4], pB[4];
        #pragma unroll
        for (int s = 0; s < 4; s++) {
            const uint4* ent = &s_ent[s * 128];
            const int n0 = s_cnt[s * 2];
            const int n1 = s_cnt[s * 2 + 1];
            float aA = 0.f, aB = 0.f;

            int i = 0;
            for (; i + 4 <= n0; i += 4) {
                uint4 e0 = ent[i], e1 = ent[i + 1], e2 = ent[i + 2], e3 = ent[i + 3];
                float w0 = *(const float*)(colc + e0.x);
                float w1 = *(const float*)(colc + e1.x);
                float w2 = *(const float*)(colc + e2.x);
                float w3 = *(const float*)(colc + e3.x);
                aA = fmaf(__uint_as_float(e0.y), w0, aA);
                aB = fmaf(__uint_as_float(e0.z), w0, aB);
                aA = fmaf(__uint_as_float(e1.y), w1, aA);
                aB = fmaf(__uint_as_float(e1.z), w1, aB);
                aA = fmaf(__uint_as_float(e2.y), w2, aA);
                aB = fmaf(__uint_as_float(e2.z), w2, aB);
                aA = fmaf(__uint_as_float(e3.y), w3, aA);
                aB = fmaf(__uint_as_float(e3.z), w3, aB);
            }
            for (; i < n0; i++) {
                uint4 e = ent[i];
                float w = *(const float*)(colc + e.x);
                aA = fmaf(__uint_as_float(e.y), w, aA);
                aB = fmaf(__uint_as_float(e.z), w, aB);
            }

            const uint4* entg = ent + 24;
            i = 0;
            for (; i + 4 <= n1; i += 4) {
                uint4 e0 = entg[i], e1 = entg[i + 1], e2 = entg[i + 2], e3 = entg[i + 3];
                float w0 = *(const float*)(colg + e0.x);
                float w1 = *(const float*)(colg + e1.x);
                float w2 = *(const float*)(colg + e2.x);
                float w3 = *(const float*)(colg + e3.x);
                aA = fmaf(__uint_as_float(e0.y), w0, aA);
                aB = fmaf(__uint_as_float(e0.z), w0, aB);
                aA = fmaf(__uint_as_float(e1.y), w1, aA);
                aB = fmaf(__uint_as_float(e1.z), w1, aB);
                aA = fmaf(__uint_as_float(e2.y), w2, aA);
                aB = fmaf(__uint_as_float(e2.z), w2, aB);
                aA = fmaf(__uint_as_float(e3.y), w3, aA);
                aB = fmaf(__uint_as_float(e3.z), w3, aB);
            }
            for (; i < n1; i++) {
                uint4 e = entg[i];
                float w = *(const float*)(colg + e.x);
                aA = fmaf(__uint_as_float(e.y), w, aA);
                aB = fmaf(__uint_as_float(e.z), w, aB);
            }
            pA[s] = aA; pB[s] = aB;
        }
        float recA = __fadd_rn(__fadd_rn(__fadd_rn(pA[0], pA[1]), pA[2]), pA[3]);
        float recB = __fadd_rn(__fadd_rn(__fadd_rn(pB[0], pB[1]), pB[2]), pB[3]);

        // ---- frozen contracted step tree (both batches) ----
        float nbA  = fmaf(decay_b, bA, __fmul_rn(omdb, zA));
        float thrA = fmaf(nbA, 1.6f, 0.01f);
        float itA  = __fadd_rn(inpA, recA);
        float nvA  = fmaf(-zA, thrA, fmaf(decay, vA, __fmul_rn(omd, itA)));
        float znA  = (nvA > thrA) ? 1.0f : 0.0f;

        float nbB  = fmaf(decay_b, bB, __fmul_rn(omdb, zB));
        float thrB = fmaf(nbB, 1.6f, 0.01f);
        float itB  = __fadd_rn(inpB, recB);
        float nvB  = fmaf(-zB, thrB, fmaf(decay, vB, __fmul_rn(omd, itB)));
        float znB  = (nvB > thrB) ? 1.0f : 0.0f;

        vA = nvA; bA = nbA; zA = znA;
        vB = nvB; bB = nbB; zB = znB;
        __stcs(optrA + (size_t)t * UNITS, znA);
        __stcs(optrB + (size_t)t * UNITS, znB);

        // publish next-step masks into the other buffer
        unsigned balA = __ballot_sync(0xffffffffu, znA != 0.f);
        unsigned balB = __ballot_sync(0xffffffffu, znB != 0.f);
        if (lane == 0) {
            s_mask[(buf ^ 1) * 32 + warp]      = balA;
            s_mask[(buf ^ 1) * 32 + 16 + warp] = balB;
        }
        __syncthreads();
    }
}

// ---------------------------------------------------------------------------
extern "C" void kernel_launch(void* const* d_in, const int* in_sizes, int n_in,
                              void* d_out, int out_size) {
    const float* x     = (const float*)d_in[0];   // [B, T, N_IN]
    const float* W_in  = (const float*)d_in[1];   // [N_IN, UNITS]
    const float* W_rec = (const float*)d_in[2];   // [UNITS, UNITS]
    float* out = (float*)d_out;                   // [B, T, UNITS]

    (void)in_sizes; (void)n_in; (void)out_size;

    // frozen correctly-rounded fp32 constants
    float decay   = (float)exp(-1.0 / 20.0);
    float decay_b = (float)exp(-1.0 / 200.0);
    float omd     = 1.0f - decay;
    float omdb    = 1.0f - decay_b;

    cudaFuncSetAttribute(scan_kernel,
                         cudaFuncAttributeMaxDynamicSharedMemorySize, SMEM_TOTAL);

    prep_wrec_kernel<<<256, 1024>>>(W_rec);

    dim3 ggrid(UNITS / GTN, (BB * TT) / GTM);     // (4, 2000)
    gemm_kernel<<<ggrid, 256>>>(x, W_in);

    scan_kernel<<<BB / 2, 512, SMEM_TOTAL>>>(out, decay, omd, decay_b, omdb);
}

// round 15
// speedup vs baseline: 1.4608x; 1.4608x over previous
#include <cuda_runtime.h>
#include <math.h>
#include <stdint.h>

#define BB    256
#define TT    1000
#define NIN   128
#define UNITS 512

#define CGS   8      // column groups (64 cols each)
#define GRPS  16     // batch groups
#define GBAT  16     // batches per group
#define CCOLS 64     // cols per CTA

// dynamic smem layout
#define SW_BYTES   (UNITS * CCOLS * 4)              // 131072
#define OFF_LIST   SW_BYTES                         // int [16][4][128]
#define OFF_CNT    (OFF_LIST + GBAT * 4 * 128 * 4)  // int [16][4]
#define SMEM_TOTAL (OFF_CNT + GBAT * 4 * 4)         // 164352

// scratch
__device__ float    g_iin[(size_t)BB * TT * UNITS];
__device__ float    g_wrec[(size_t)UNITS * UNITS];
__device__ unsigned g_masks[2][GRPS][GBAT][16];   // [parity][grp][batch][word]
__device__ int      g_sync[GRPS];

// ---------------------------------------------------------------------------
// Prep: diag-zeroed W_rec copy + zero group sync counters (each launch/replay).
// ---------------------------------------------------------------------------
__global__ void prep_kernel(const float* __restrict__ W_rec) {
    int idx = blockIdx.x * blockDim.x + threadIdx.x;
    int row = idx >> 9, col = idx & 511;
    g_wrec[idx] = (row == col) ? 0.0f : W_rec[idx];
    if (blockIdx.x == 0 && threadIdx.x < GRPS) g_sync[threadIdx.x] = 0;
}

// ---------------------------------------------------------------------------
// Phase 1: i_in = X @ W_in — bit-frozen serial ascending-k FMA chain.
// ---------------------------------------------------------------------------
#define GTM 128
#define GTN 128
#define GTK 32

__global__ __launch_bounds__(256) void gemm_kernel(const float* __restrict__ X,
                                                   const float* __restrict__ Wm) {
    __shared__ float As[GTK][GTM + 4];
    __shared__ float Bs[GTK][GTN];
    const int bm = blockIdx.y * GTM;
    const int bn = blockIdx.x * GTN;
    const int tid = threadIdx.x;
    const int tx = tid & 15, ty = tid >> 4;

    float acc[8][8] = {};

    for (int kc = 0; kc < NIN; kc += GTK) {
        #pragma unroll
        for (int i = 0; i < 4; i++) {
            int idx = tid + i * 256;
            int m  = idx >> 3;
            int k4 = idx & 7;
            float4 vv = *(const float4*)(X + (size_t)(bm + m) * NIN + kc + k4 * 4);
            As[k4 * 4 + 0][m] = vv.x;
            As[k4 * 4 + 1][m] = vv.y;
            As[k4 * 4 + 2][m] = vv.z;
            As[k4 * 4 + 3][m] = vv.w;
        }
        #pragma unroll
        for (int i = 0; i < 4; i++) {
            int idx = tid + i * 256;
            int k  = idx >> 5;
            int n4 = idx & 31;
            *(float4*)(&Bs[k][n4 * 4]) =
                *(const float4*)(Wm + (size_t)(kc + k) * UNITS + bn + n4 * 4);
        }
        __syncthreads();

        #pragma unroll
        for (int k = 0; k < GTK; k++) {
            float a[8], b[8];
            *(float4*)(a)     = *(const float4*)(&As[k][ty * 8]);
            *(float4*)(a + 4) = *(const float4*)(&As[k][ty * 8 + 4]);
            *(float4*)(b)     = *(const float4*)(&Bs[k][tx * 8]);
            *(float4*)(b + 4) = *(const float4*)(&Bs[k][tx * 8 + 4]);
            #pragma unroll
            for (int i = 0; i < 8; i++)
                #pragma unroll
                for (int j = 0; j < 8; j++)
                    acc[i][j] = fmaf(a[i], b[j], acc[i][j]);
        }
        __syncthreads();
    }

    #pragma unroll
    for (int i = 0; i < 8; i++) {
        float* crow = g_iin + (size_t)(bm + ty * 8 + i) * UNITS + bn + tx * 8;
        __stcs((float4*)(crow),     *(float4*)(&acc[i][0]));
        __stcs((float4*)(crow + 4), *(float4*)(&acc[i][4]));
    }
}

// ---------------------------------------------------------------------------
// Phase 2: ALIF scan, SMEM-resident W_rec column slice.
// CTA = (colgroup cg, batchgroup grp): 64 cols x 16 batches; 128 CTAs,
// 164 KB smem -> 1 CTA/SM, all wave-1 resident (spin-sync safe).
// warp = batch, lane = column-pair. Weights via LDS. Frozen arithmetic:
// per-slice ascending (word, bit-in-byte) fadd chain, ((p0+p1)+p2)+p3,
// contracted step tree — bit-identical to the passing R8/R9 recipe.
// Cross-CTA spike exchange: double-buffered gmem masks + per-group counter.
// ---------------------------------------------------------------------------
__device__ __forceinline__ unsigned expand16(unsigned x) {
    x &= 0xFFFFu;
    x = (x | (x << 8)) & 0x00FF00FFu;
    x = (x | (x << 4)) & 0x0F0F0F0Fu;
    x = (x | (x << 2)) & 0x33333333u;
    x = (x | (x << 1)) & 0x55555555u;
    return x;
}

__device__ __forceinline__ int ldacq(const int* p) {
    int v;
    asm volatile("ld.global.acquire.gpu.s32 %0, [%1];" : "=r"(v) : "l"(p));
    return v;
}

extern __shared__ char s_dyn[];

__global__ __launch_bounds__(512) void scan_kernel(float* __restrict__ out,
                                                   float decay, float omd,
                                                   float decay_b, float omdb) {
    float* s_w    = (float*)s_dyn;                 // [512 rows][64 cols]
    int*   s_list = (int*)(s_dyn + OFF_LIST);      // [16][4][128]
    int*   s_cnt  = (int*)(s_dyn + OFF_CNT);       // [16][4]

    const int tid  = threadIdx.x;
    const int cg   = blockIdx.x & 7;               // column group
    const int grp  = blockIdx.x >> 3;              // batch group
    const int b    = tid >> 5;                     // warp = local batch
    const int lane = tid & 31;                     // column pair
    const int B    = grp * GBAT + b;               // global batch

    // load W_rec[:, cg*64 .. +64) into smem
    {
        const float* src = g_wrec + cg * CCOLS;
        for (int i = tid; i < UNITS * (CCOLS / 4); i += 512) {
            int row = i >> 4, q = i & 15;
            *(float4*)(s_w + row * CCOLS + q * 4) =
                *(const float4*)(src + (size_t)row * UNITS + q * 4);
        }
    }
    __syncthreads();

    float v0 = 0.f, ba0 = 0.f, z0 = 0.f;
    float v1 = 0.f, ba1 = 0.f, z1 = 0.f;

    const char* wbase = (const char*)s_w + (lane << 3);
    const float* iptr = g_iin + (size_t)B * TT * UNITS + cg * CCOLS + lane * 2;
    float*       optr = out   + (size_t)B * TT * UNITS + cg * CCOLS + lane * 2;
    int* listb = s_list + b * 4 * 128;

    for (int t = 0; t < TT; t++) {
        float2 inp = *(const float2*)(iptr + (size_t)t * UNITS);

        // ---- wait for all 8 col-CTAs of this group to publish step t-1,
        //      then read this batch's 16 mask words ----
        unsigned word = 0u;
        if (t > 0) {
            if (tid == 0) {
                const int target = 8 * t;
                while (ldacq(&g_sync[grp]) < target) __nanosleep(60);
            }
            __syncthreads();
            if (lane < 16) {
                asm volatile("ld.global.cg.u32 %0, [%1];"
                             : "=r"(word)
                             : "l"(&g_masks[(t - 1) & 1][grp][b][lane]));
            }
        }

        // ---- compact 4 slice lists in frozen ascending (word,bit) order ----
        #pragma unroll
        for (int s = 0; s < 4; s++) {
            unsigned byte = (lane < 16) ? ((word >> (s * 8)) & 0xFFu) : 0u;
            int c  = __popc(byte);
            int sc = c;
            #pragma unroll
            for (int off = 1; off < 32; off <<= 1) {
                int nbr = __shfl_up_sync(0xffffffffu, sc, off);
                if (lane >= off) sc += nbr;
            }
            int pos = sc - c;
            unsigned mm = byte;
            int* dst = listb + s * 128;
            while (mm) {
                int j = __ffs(mm) - 1; mm &= mm - 1;
                dst[pos++] = (lane * 32 + s * 8 + j) << 8;   // row * 256 bytes
            }
            if (lane == 15) s_cnt[b * 4 + s] = sc;
        }
        __syncwarp();      // warp-private lists; warp-scope visibility is enough

        // ---- per-slice sums from smem weights, frozen order ----
        float p0[4], p1[4];
        #pragma unroll
        for (int s = 0; s < 4; s++) {
            const int n = s_cnt[b * 4 + s];
            const int* il = listb + s * 128;
            float a0 = 0.f, a1 = 0.f;
            int i = 0;
            for (; i + 4 <= n; i += 4) {
                int4 e = *(const int4*)(il + i);
                float2 w0 = *(const float2*)(wbase + e.x);
                float2 w1 = *(const float2*)(wbase + e.y);
                float2 w2 = *(const float2*)(wbase + e.z);
                float2 w3 = *(const float2*)(wbase + e.w);
                a0 = __fadd_rn(a0, w0.x); a1 = __fadd_rn(a1, w0.y);
                a0 = __fadd_rn(a0, w1.x); a1 = __fadd_rn(a1, w1.y);
                a0 = __fadd_rn(a0, w2.x); a1 = __fadd_rn(a1, w2.y);
                a0 = __fadd_rn(a0, w3.x); a1 = __fadd_rn(a1, w3.y);
            }
            for (; i < n; i++) {
                float2 w = *(const float2*)(wbase + il[i]);
                a0 = __fadd_rn(a0, w.x); a1 = __fadd_rn(a1, w.y);
            }
            p0[s] = a0; p1[s] = a1;
        }
        float rec0 = __fadd_rn(__fadd_rn(__fadd_rn(p0[0], p0[1]), p0[2]), p0[3]);
        float rec1 = __fadd_rn(__fadd_rn(__fadd_rn(p1[0], p1[1]), p1[2]), p1[3]);

        // ---- frozen contracted step tree (both cols) ----
        float nb0  = fmaf(decay_b, ba0, __fmul_rn(omdb, z0));
        float thr0 = fmaf(nb0, 1.6f, 0.01f);
        float it0  = __fadd_rn(inp.x, rec0);
        float nv0  = fmaf(-z0, thr0, fmaf(decay, v0, __fmul_rn(omd, it0)));
        float zn0  = (nv0 > thr0) ? 1.0f : 0.0f;

        float nb1  = fmaf(decay_b, ba1, __fmul_rn(omdb, z1));
        float thr1 = fmaf(nb1, 1.6f, 0.01f);
        float it1  = __fadd_rn(inp.y, rec1);
        float nv1  = fmaf(-z1, thr1, fmaf(decay, v1, __fmul_rn(omd, it1)));
        float zn1  = (nv1 > thr1) ? 1.0f : 0.0f;

        v0 = nv0; ba0 = nb0; z0 = zn0;
        v1 = nv1; ba1 = nb1; z1 = zn1;
        {
            float2 zz = make_float2(zn0, zn1);
            __stcs((float2*)(optr + (size_t)t * UNITS), zz);
        }

        // ---- publish this CTA's 2 mask words per batch (Morton interleave:
        //      word cg*2 covers local cols 0..31, cg*2+1 covers 32..63) ----
        unsigned bal0 = __ballot_sync(0xffffffffu, zn0 != 0.f);
        unsigned bal1 = __ballot_sync(0xffffffffu, zn1 != 0.f);
        if (lane == 0) {
            unsigned w0 = expand16(bal0)       | (expand16(bal1) << 1);
            unsigned w1 = expand16(bal0 >> 16) | (expand16(bal1 >> 16) << 1);
            unsigned* dst = &g_masks[t & 1][grp][b][cg * 2];
            asm volatile("st.global.cg.v2.u32 [%0], {%1, %2};"
                         :: "l"(dst), "r"(w0), "r"(w1));
        }
        __syncthreads();    // all 16 warps' mask stores issued
        if (tid == 0) {
            __threadfence();                  // stores visible before count
            atomicAdd(&g_sync[grp], 1);
        }
    }
}

// ---------------------------------------------------------------------------
extern "C" void kernel_launch(void* const* d_in, const int* in_sizes, int n_in,
                              void* d_out, int out_size) {
    const float* x     = (const float*)d_in[0];   // [B, T, N_IN]
    const float* W_in  = (const float*)d_in[1];   // [N_IN, UNITS]
    const float* W_rec = (const float*)d_in[2];   // [UNITS, UNITS]
    float* out = (float*)d_out;                   // [B, T, UNITS]

    (void)in_sizes; (void)n_in; (void)out_size;

    // frozen correctly-rounded fp32 constants
    float decay   = (float)exp(-1.0 / 20.0);
    float decay_b = (float)exp(-1.0 / 200.0);
    float omd     = 1.0f - decay;
    float omdb    = 1.0f - decay_b;

    cudaFuncSetAttribute(scan_kernel,
                         cudaFuncAttributeMaxDynamicSharedMemorySize, SMEM_TOTAL);

    prep_kernel<<<256, 1024>>>(W_rec);

    dim3 ggrid(UNITS / GTN, (BB * TT) / GTM);     // (4, 2000)
    gemm_kernel<<<ggrid, 256>>>(x, W_in);

    scan_kernel<<<CGS * GRPS, 512, SMEM_TOTAL>>>(out, decay, omd, decay_b, omdb);
}